// round 6
// baseline (speedup 1.0000x reference)
#include <cuda_runtime.h>
#include <cuda_bf16.h>
#include <cstdint>

#define D 128
#define NMAX 50048
#define EMAX 800000
#define RPB 16   // rows per gemm block (8 packed pairs)

// Scratch (static device arrays; no allocation anywhere)
__device__ float g_h[(size_t)NMAX * D];     // per-layer transformed features
__device__ float g_agg[(size_t)NMAX * D];   // layer-1 aggregated output
__device__ float g_dinv[NMAX];              // rsqrt(deg+1)
__device__ int   g_deg[NMAX];
__device__ int   g_off[NMAX + 1];           // CSR row offsets (by dst)
__device__ int   g_cur[NMAX];               // fill cursors
__device__ int   g_src[EMAX];
__device__ int   g_dst[EMAX];
__device__ int2  g_ce[EMAX];                // CSR entries: (src, bits(dinv[src]))

// ---------------------------------------------------------------------------
// packed dual-fp32 fma (PTX-only; ptxas won't auto-fuse)
// ---------------------------------------------------------------------------
__device__ __forceinline__ unsigned long long ffma2(unsigned long long a,
                                                    unsigned long long b,
                                                    unsigned long long c) {
    unsigned long long d;
    asm("fma.rn.f32x2 %0, %1, %2, %3;" : "=l"(d) : "l"(a), "l"(b), "l"(c));
    return d;
}

__global__ void k_zero_deg(int n) {
    int i = blockIdx.x * blockDim.x + threadIdx.x;
    if (i < n) g_deg[i] = 0;
}

// decode edges (int64 or int32, detected per-block) + degree count
__global__ void k_decode(const void* __restrict__ ei, int E, int n) {
    __shared__ int s_is64;
    if (threadIdx.x == 0) {
        const int* p = (const int*)ei;
        int az = 1;
        #pragma unroll
        for (int i = 1; i < 32; i += 2)
            if (p[i] != 0) az = 0;
        s_is64 = az;
    }
    __syncthreads();

    int i = blockIdx.x * blockDim.x + threadIdx.x;
    if (i >= E) return;
    int s, d;
    if (s_is64) {
        const long long* p = (const long long*)ei;
        s = (int)p[i];
        d = (int)p[(size_t)E + i];
    } else {
        const int* p = (const int*)ei;
        s = p[i];
        d = p[E + i];
    }
    s = min(max(s, 0), n - 1);
    d = min(max(d, 0), n - 1);
    g_src[i] = s;
    g_dst[i] = d;
    atomicAdd(&g_deg[d], 1);
}

// ---------------------------------------------------------------------------
// single-block exclusive scan of g_deg -> g_off/g_cur, plus dinv = rsqrt(deg+1)
// ---------------------------------------------------------------------------
__global__ void k_scan(int n) {
    __shared__ int warp_sums[32];
    const int t = threadIdx.x;                 // 1024 threads
    const int chunk = (n + 1023) >> 10;
    const int begin = t * chunk;
    const int end   = min(begin + chunk, n);

    int s = 0;
    for (int i = begin; i < end; i++) s += g_deg[i];

    const int lane = t & 31, w = t >> 5;
    int v = s;
    #pragma unroll
    for (int o = 1; o < 32; o <<= 1) {
        int x = __shfl_up_sync(0xFFFFFFFFu, v, o);
        if (lane >= o) v += x;
    }
    if (lane == 31) warp_sums[w] = v;
    __syncthreads();
    if (w == 0) {
        int ws = warp_sums[lane];
        #pragma unroll
        for (int o = 1; o < 32; o <<= 1) {
            int x = __shfl_up_sync(0xFFFFFFFFu, ws, o);
            if (lane >= o) ws += x;
        }
        warp_sums[lane] = ws;
    }
    __syncthreads();
    int run = (v - s) + (w > 0 ? warp_sums[w - 1] : 0);

    for (int i = begin; i < end; i++) {
        int dg = g_deg[i];
        g_off[i] = run;
        g_cur[i] = run;
        g_dinv[i] = rsqrtf((float)dg + 1.0f);
        run += dg;
    }
    if (end == n && begin < n) g_off[n] = run;
}

// fill CSR: entry = (src, dinv[src])
__global__ void k_fill(int E) {
    int i = blockIdx.x * blockDim.x + threadIdx.x;
    if (i >= E) return;
    int s = g_src[i];
    int pos = atomicAdd(&g_cur[g_dst[i]], 1);
    g_ce[pos] = make_int2(s, __float_as_int(g_dinv[s]));
}

// ---------------------------------------------------------------------------
// GEMM: g_h[row][j] = sum_k in'[row][k] * W[k][j]   via packed f32x2 FMA
//   in' = relu(in) if relu_in; in = x_or_null ?: g_agg
// blockDim = 128 (t = output column), 16 rows (8 packed pairs) per block.
// ---------------------------------------------------------------------------
__global__ void k_gemm(const float* __restrict__ x_or_null,
                       const float* __restrict__ W,
                       int relu_in, int n)
{
    const float* in = x_or_null ? x_or_null : g_agg;

    __shared__ float s[D][RPB];   // s[k][r]; row-pairs are 8B-aligned
    const int t = threadIdx.x;
    const int row0 = blockIdx.x * RPB;

#pragma unroll
    for (int r = 0; r < RPB; r++) {
        int row = row0 + r;
        float v = 0.0f;
        if (row < n) {
            v = in[(size_t)row * D + t];
            if (relu_in) v = fmaxf(v, 0.0f);
        }
        s[t][r] = v;
    }
    __syncthreads();

    unsigned long long acc[8];
#pragma unroll
    for (int p = 0; p < 8; p++)
        asm("mov.b64 %0, {%1, %1};" : "=l"(acc[p]) : "f"(0.0f));

    const unsigned sb = (unsigned)__cvta_generic_to_shared(&s[0][0]);

#pragma unroll 8
    for (int k = 0; k < D; k++) {
        float w = W[k * D + t];                  // coalesced; L1-resident
        unsigned long long wd;
        asm("mov.b64 %0, {%1, %1};" : "=l"(wd) : "f"(w));

        unsigned a = sb + k * (RPB * 4);
        unsigned long long p0, p1, p2, p3, p4, p5, p6, p7;
        asm("ld.shared.v2.b64 {%0, %1}, [%2];" : "=l"(p0), "=l"(p1) : "r"(a));
        asm("ld.shared.v2.b64 {%0, %1}, [%2];" : "=l"(p2), "=l"(p3) : "r"(a + 16));
        asm("ld.shared.v2.b64 {%0, %1}, [%2];" : "=l"(p4), "=l"(p5) : "r"(a + 32));
        asm("ld.shared.v2.b64 {%0, %1}, [%2];" : "=l"(p6), "=l"(p7) : "r"(a + 48));

        acc[0] = ffma2(p0, wd, acc[0]);
        acc[1] = ffma2(p1, wd, acc[1]);
        acc[2] = ffma2(p2, wd, acc[2]);
        acc[3] = ffma2(p3, wd, acc[3]);
        acc[4] = ffma2(p4, wd, acc[4]);
        acc[5] = ffma2(p5, wd, acc[5]);
        acc[6] = ffma2(p6, wd, acc[6]);
        acc[7] = ffma2(p7, wd, acc[7]);
    }

#pragma unroll
    for (int p = 0; p < 8; p++) {
        float lo, hi;
        asm("mov.b64 {%0, %1}, %2;" : "=f"(lo), "=f"(hi) : "l"(acc[p]));
        int r0 = row0 + 2 * p;
        if (r0 < n)     g_h[(size_t)r0 * D + t] = lo;
        if (r0 + 1 < n) g_h[(size_t)(r0 + 1) * D + t] = hi;
    }
}

// ---------------------------------------------------------------------------
// Gather-aggregate: one warp per dst row, lane owns one float4 of 128 cols.
// out[d] = dinv[d] * sum_{e in CSR[d]} dinv[src]*h[src] + dinv[d]^2*h[d] + b
// ---------------------------------------------------------------------------
__global__ void k_agg(float* __restrict__ out_or_null,
                      const float* __restrict__ b, int n)
{
    float* out = out_or_null ? out_or_null : g_agg;

    const int warp = (blockIdx.x * blockDim.x + threadIdx.x) >> 5;
    const int lane = threadIdx.x & 31;
    if (warp >= n) return;

    const int d   = warp;
    const int beg = g_off[d];
    const int end = g_off[d + 1];

    float4 acc = make_float4(0.f, 0.f, 0.f, 0.f);
    int j = beg;
    for (; j + 2 <= end; j += 2) {            // unroll x2 for load MLP
        int2 e0 = __ldg(&g_ce[j]);
        int2 e1 = __ldg(&g_ce[j + 1]);
        float w0 = __int_as_float(e0.y);
        float w1 = __int_as_float(e1.y);
        const float4 v0 = *(const float4*)&g_h[(size_t)e0.x * D + lane * 4];
        const float4 v1 = *(const float4*)&g_h[(size_t)e1.x * D + lane * 4];
        acc.x = fmaf(w0, v0.x, fmaf(w1, v1.x, acc.x));
        acc.y = fmaf(w0, v0.y, fmaf(w1, v1.y, acc.y));
        acc.z = fmaf(w0, v0.z, fmaf(w1, v1.z, acc.z));
        acc.w = fmaf(w0, v0.w, fmaf(w1, v1.w, acc.w));
    }
    if (j < end) {
        int2 e = __ldg(&g_ce[j]);
        float w = __int_as_float(e.y);
        const float4 v = *(const float4*)&g_h[(size_t)e.x * D + lane * 4];
        acc.x = fmaf(w, v.x, acc.x);
        acc.y = fmaf(w, v.y, acc.y);
        acc.z = fmaf(w, v.z, acc.z);
        acc.w = fmaf(w, v.w, acc.w);
    }

    const float di  = g_dinv[d];
    const float di2 = di * di;
    const float4 hv = *(const float4*)&g_h[(size_t)d * D + lane * 4];
    const float4 bv = *(const float4*)&b[lane * 4];

    float4 o;
    o.x = fmaf(di, acc.x, fmaf(di2, hv.x, bv.x));
    o.y = fmaf(di, acc.y, fmaf(di2, hv.y, bv.y));
    o.z = fmaf(di, acc.z, fmaf(di2, hv.z, bv.z));
    o.w = fmaf(di, acc.w, fmaf(di2, hv.w, bv.w));
    *(float4*)&out[(size_t)d * D + lane * 4] = o;
}

// ---------------------------------------------------------------------------
// launch
// ---------------------------------------------------------------------------
extern "C" void kernel_launch(void* const* d_in, const int* in_sizes, int n_in,
                              void* d_out, int out_size)
{
    const float* x   = (const float*)d_in[0];
    const void*  ei  = d_in[1];
    const float* W1  = (const float*)d_in[2];
    const float* b1  = (const float*)d_in[3];
    const float* W2  = (const float*)d_in[4];
    const float* b2  = (const float*)d_in[5];
    float*       out = (float*)d_out;

    const int N = in_sizes[0] / D;
    const int E = in_sizes[1] / 2;

    const int TPB = 256;
    const int eb  = (E + TPB - 1) / TPB;
    const int nb  = (N + TPB - 1) / TPB;

    // preprocessing: decode(+detect) -> scan(+dinv) -> CSR fill
    k_zero_deg<<<nb, TPB>>>(N);
    k_decode<<<eb, TPB>>>(ei, E, N);
    k_scan<<<1, 1024>>>(N);
    k_fill<<<eb, TPB>>>(E);

    const int gemm_blocks = (N + RPB - 1) / RPB;
    const int agg_blocks  = (N * 32 + TPB - 1) / TPB;   // one warp per row

    // layer 1: h1 = x @ W1 ; agg1 = gather(h1) + b1
    k_gemm<<<gemm_blocks, D>>>(x, W1, 0, N);
    k_agg<<<agg_blocks, TPB>>>(nullptr, b1, N);

    // layer 2: h2 = relu(agg1) @ W2 ; out = gather(h2) + b2
    k_gemm<<<gemm_blocks, D>>>(nullptr, W2, 1, N);
    k_agg<<<agg_blocks, TPB>>>(out, b2, N);
}

// round 7
// speedup vs baseline: 1.1224x; 1.1224x over previous
#include <cuda_runtime.h>
#include <cuda_bf16.h>
#include <cstdint>

#define D 128
#define NMAX 50048
#define EMAX 800000
#define RPB 8   // rows per gemm block

// Scratch (static device arrays; no allocation anywhere)
__device__ float g_h[(size_t)NMAX * D];     // per-layer transformed features
__device__ float g_agg[(size_t)NMAX * D];   // layer-1 aggregated output
__device__ float g_dinv[NMAX];              // rsqrt(deg+1)
__device__ int   g_deg[NMAX];
__device__ int   g_off[NMAX + 1];           // CSR row offsets (by dst)
__device__ int   g_cur[NMAX];               // fill cursors
__device__ int   g_src[EMAX];
__device__ int   g_dst[EMAX];
__device__ int2  g_ce[EMAX];                // CSR entries: (src, bits(dinv[src]))

__global__ void k_zero_deg(int n) {
    int i = blockIdx.x * blockDim.x + threadIdx.x;
    if (i < n) g_deg[i] = 0;
}

// decode edges (int64 or int32, detected per-block) + degree count
__global__ void k_decode(const void* __restrict__ ei, int E, int n) {
    __shared__ int s_is64;
    if (threadIdx.x == 0) {
        const int* p = (const int*)ei;
        int az = 1;
        #pragma unroll
        for (int i = 1; i < 32; i += 2)
            if (p[i] != 0) az = 0;
        s_is64 = az;
    }
    __syncthreads();

    int i = blockIdx.x * blockDim.x + threadIdx.x;
    if (i >= E) return;
    int s, d;
    if (s_is64) {
        const long long* p = (const long long*)ei;
        s = (int)p[i];
        d = (int)p[(size_t)E + i];
    } else {
        const int* p = (const int*)ei;
        s = p[i];
        d = p[E + i];
    }
    s = min(max(s, 0), n - 1);
    d = min(max(d, 0), n - 1);
    g_src[i] = s;
    g_dst[i] = d;
    atomicAdd(&g_deg[d], 1);
}

// ---------------------------------------------------------------------------
// single-block exclusive scan of g_deg -> g_off/g_cur, plus dinv = rsqrt(deg+1)
// ---------------------------------------------------------------------------
__global__ void k_scan(int n) {
    __shared__ int warp_sums[32];
    const int t = threadIdx.x;                 // 1024 threads
    const int chunk = (n + 1023) >> 10;
    const int begin = t * chunk;
    const int end   = min(begin + chunk, n);

    int s = 0;
    for (int i = begin; i < end; i++) s += g_deg[i];

    const int lane = t & 31, w = t >> 5;
    int v = s;
    #pragma unroll
    for (int o = 1; o < 32; o <<= 1) {
        int x = __shfl_up_sync(0xFFFFFFFFu, v, o);
        if (lane >= o) v += x;
    }
    if (lane == 31) warp_sums[w] = v;
    __syncthreads();
    if (w == 0) {
        int ws = warp_sums[lane];
        #pragma unroll
        for (int o = 1; o < 32; o <<= 1) {
            int x = __shfl_up_sync(0xFFFFFFFFu, ws, o);
            if (lane >= o) ws += x;
        }
        warp_sums[lane] = ws;
    }
    __syncthreads();
    int run = (v - s) + (w > 0 ? warp_sums[w - 1] : 0);

    for (int i = begin; i < end; i++) {
        int dg = g_deg[i];
        g_off[i] = run;
        g_cur[i] = run;
        g_dinv[i] = rsqrtf((float)dg + 1.0f);
        run += dg;
    }
    if (end == n && begin < n) g_off[n] = run;
}

// fill CSR: entry = (src, dinv[src])
__global__ void k_fill(int E) {
    int i = blockIdx.x * blockDim.x + threadIdx.x;
    if (i >= E) return;
    int s = g_src[i];
    int pos = atomicAdd(&g_cur[g_dst[i]], 1);
    g_ce[pos] = make_int2(s, __float_as_int(g_dinv[s]));
}

// ---------------------------------------------------------------------------
// GEMM (R4-proven): g_h[row][j] = sum_k in'[row][k] * W[k][j]
//   in' = relu(in) if relu_in; in = x_or_null ?: g_agg
// blockDim = 128 (one thread per output column), RPB=8 rows per block.
// ---------------------------------------------------------------------------
__global__ void k_gemm(const float* __restrict__ x_or_null,
                       const float* __restrict__ W,
                       int relu_in, int n)
{
    const float* in = x_or_null ? x_or_null : g_agg;

    __shared__ float s[D][RPB];   // transposed: s[k][r]
    const int t = threadIdx.x;
    const int row0 = blockIdx.x * RPB;

#pragma unroll
    for (int r = 0; r < RPB; r++) {
        int row = row0 + r;
        float v = 0.0f;
        if (row < n) {
            v = in[(size_t)row * D + t];
            if (relu_in) v = fmaxf(v, 0.0f);
        }
        s[t][r] = v;
    }
    __syncthreads();

    float acc[RPB];
#pragma unroll
    for (int r = 0; r < RPB; r++) acc[r] = 0.0f;

#pragma unroll 4
    for (int k = 0; k < D; k++) {
        float w = W[k * D + t];                 // coalesced across threads
        float4 a0 = *(const float4*)&s[k][0];   // broadcast LDS.128
        float4 a1 = *(const float4*)&s[k][4];
        acc[0] = fmaf(a0.x, w, acc[0]);
        acc[1] = fmaf(a0.y, w, acc[1]);
        acc[2] = fmaf(a0.z, w, acc[2]);
        acc[3] = fmaf(a0.w, w, acc[3]);
        acc[4] = fmaf(a1.x, w, acc[4]);
        acc[5] = fmaf(a1.y, w, acc[5]);
        acc[6] = fmaf(a1.z, w, acc[6]);
        acc[7] = fmaf(a1.w, w, acc[7]);
    }

#pragma unroll
    for (int r = 0; r < RPB; r++) {
        int row = row0 + r;
        if (row >= n) break;
        g_h[(size_t)row * D + t] = acc[r];
    }
}

// ---------------------------------------------------------------------------
// Gather-aggregate: one warp per dst row, lane owns one float4 of 128 cols.
// out[d] = dinv[d] * sum_{e in CSR[d]} dinv[src]*h[src] + dinv[d]^2*h[d] + b
// Unroll x4 for gather MLP (avg degree ~16).
// ---------------------------------------------------------------------------
__global__ void k_agg(float* __restrict__ out_or_null,
                      const float* __restrict__ b, int n)
{
    float* out = out_or_null ? out_or_null : g_agg;

    const int warp = (blockIdx.x * blockDim.x + threadIdx.x) >> 5;
    const int lane = threadIdx.x & 31;
    if (warp >= n) return;

    const int d   = warp;
    const int beg = g_off[d];
    const int end = g_off[d + 1];

    float4 acc = make_float4(0.f, 0.f, 0.f, 0.f);
    int j = beg;
    for (; j + 4 <= end; j += 4) {
        int2 e0 = __ldg(&g_ce[j]);
        int2 e1 = __ldg(&g_ce[j + 1]);
        int2 e2 = __ldg(&g_ce[j + 2]);
        int2 e3 = __ldg(&g_ce[j + 3]);
        float w0 = __int_as_float(e0.y);
        float w1 = __int_as_float(e1.y);
        float w2 = __int_as_float(e2.y);
        float w3 = __int_as_float(e3.y);
        const float4 v0 = *(const float4*)&g_h[(size_t)e0.x * D + lane * 4];
        const float4 v1 = *(const float4*)&g_h[(size_t)e1.x * D + lane * 4];
        const float4 v2 = *(const float4*)&g_h[(size_t)e2.x * D + lane * 4];
        const float4 v3 = *(const float4*)&g_h[(size_t)e3.x * D + lane * 4];
        acc.x += w0 * v0.x + w1 * v1.x + w2 * v2.x + w3 * v3.x;
        acc.y += w0 * v0.y + w1 * v1.y + w2 * v2.y + w3 * v3.y;
        acc.z += w0 * v0.z + w1 * v1.z + w2 * v2.z + w3 * v3.z;
        acc.w += w0 * v0.w + w1 * v1.w + w2 * v2.w + w3 * v3.w;
    }
    for (; j < end; j++) {
        int2 e = __ldg(&g_ce[j]);
        float w = __int_as_float(e.y);
        const float4 v = *(const float4*)&g_h[(size_t)e.x * D + lane * 4];
        acc.x = fmaf(w, v.x, acc.x);
        acc.y = fmaf(w, v.y, acc.y);
        acc.z = fmaf(w, v.z, acc.z);
        acc.w = fmaf(w, v.w, acc.w);
    }

    const float di  = g_dinv[d];
    const float di2 = di * di;
    const float4 hv = *(const float4*)&g_h[(size_t)d * D + lane * 4];
    const float4 bv = *(const float4*)&b[lane * 4];

    float4 o;
    o.x = fmaf(di, acc.x, fmaf(di2, hv.x, bv.x));
    o.y = fmaf(di, acc.y, fmaf(di2, hv.y, bv.y));
    o.z = fmaf(di, acc.z, fmaf(di2, hv.z, bv.z));
    o.w = fmaf(di, acc.w, fmaf(di2, hv.w, bv.w));
    *(float4*)&out[(size_t)d * D + lane * 4] = o;
}

// ---------------------------------------------------------------------------
// launch
// ---------------------------------------------------------------------------
extern "C" void kernel_launch(void* const* d_in, const int* in_sizes, int n_in,
                              void* d_out, int out_size)
{
    const float* x   = (const float*)d_in[0];
    const void*  ei  = d_in[1];
    const float* W1  = (const float*)d_in[2];
    const float* b1  = (const float*)d_in[3];
    const float* W2  = (const float*)d_in[4];
    const float* b2  = (const float*)d_in[5];
    float*       out = (float*)d_out;

    const int N = in_sizes[0] / D;
    const int E = in_sizes[1] / 2;

    const int TPB = 256;
    const int eb  = (E + TPB - 1) / TPB;
    const int nb  = (N + TPB - 1) / TPB;

    // preprocessing: decode(+detect) -> scan(+dinv) -> CSR fill
    k_zero_deg<<<nb, TPB>>>(N);
    k_decode<<<eb, TPB>>>(ei, E, N);
    k_scan<<<1, 1024>>>(N);
    k_fill<<<eb, TPB>>>(E);

    const int gemm_blocks = (N + RPB - 1) / RPB;
    const int agg_blocks  = (N * 32 + TPB - 1) / TPB;   // one warp per row

    // layer 1: h1 = x @ W1 ; agg1 = gather(h1) + b1
    k_gemm<<<gemm_blocks, D>>>(x, W1, 0, N);
    k_agg<<<agg_blocks, TPB>>>(nullptr, b1, N);

    // layer 2: h2 = relu(agg1) @ W2 ; out = gather(h2) + b2
    k_gemm<<<gemm_blocks, D>>>(nullptr, W2, 1, N);
    k_agg<<<agg_blocks, TPB>>>(out, b2, N);
}